// round 16
// baseline (speedup 1.0000x reference)
#include <cuda_runtime.h>
#include <cuda_fp16.h>
#include <math.h>

#define NN 50000
#define IN_DIM 256
#define HID 32
#define NCLS 40
#define NEDGE 1600000
#define NMID 30
#define ADJCAP (NEDGE + 8 * NN)   // rows padded to multiples of 8

// ---------------- device scratch (no allocations allowed) ----------------
__device__ int    g_degc[NN], g_degr[NN];
__device__ int    g_offc[NN + 1], g_offr[NN + 1];   // 8-aligned row starts
__device__ int    g_curc[NN], g_curr[NN];
__device__ __align__(16) int g_adjc[ADJCAP];
__device__ __align__(16) int g_adjr[ADJCAP];
__device__ float  g_dinv[NN], g_cntinv[NN];
__device__ float  g_x0[NN * HID];
__device__ __align__(16) short  g_Gq[NN * HID];   // (h @ W) * dinv — int16 row-quantized
__device__ float  g_GS[NN];                       // per-node dequant scale for Gq
__device__ __align__(16) float  g_Bf[NN * HID];   // LN(relu(gcn)) — node-local fp32
__device__ __align__(16) __half g_Bh[NN * HID];   // fp16 gather copy (score path)
__device__ float  g_S[NN];           // s[j]=Σ|B-hm|·w2  — scalar gathered fp32
__device__ float  g_T[NN];           // t[i]=Σ hm·h·w0   — node-local scalar
__device__ __half g_G40h[NN * NCLS]; // final (h @ Wl) * dinv — fp16 (one layer only)

__device__ __forceinline__ float warpsum(float v) {
    #pragma unroll
    for (int o = 16; o > 0; o >>= 1) v += __shfl_xor_sync(0xffffffffu, v, o);
    return v;
}

__device__ __forceinline__ float warpmax(float v) {
    #pragma unroll
    for (int o = 16; o > 0; o >>= 1) v = fmaxf(v, __shfl_xor_sync(0xffffffffu, v, o));
    return v;
}

// quantize one per-lane value g (lane = feature) into Gq/GS for node i
__device__ __forceinline__ void quant_row(int i, int lane, float g) {
    float mx = warpmax(fabsf(g));
    float inv = (mx > 0.f) ? (32767.f / mx) : 0.f;
    g_Gq[i * HID + lane] = (short)__float2int_rn(g * inv);
    if (lane == 0) g_GS[i] = mx * (1.f / 32767.f);
}

// ---------------- setup: degrees, scans, CSR ----------------
__global__ void zero_deg() {
    for (int i = blockIdx.x * blockDim.x + threadIdx.x; i < NN;
         i += gridDim.x * blockDim.x) {
        g_degc[i] = 0;
        g_degr[i] = 0;
    }
}

__global__ void hist_edges(const int* __restrict__ ei) {
    for (int e = blockIdx.x * blockDim.x + threadIdx.x; e < NEDGE;
         e += gridDim.x * blockDim.x) {
        atomicAdd(&g_degr[ei[e]], 1);          // row
        atomicAdd(&g_degc[ei[NEDGE + e]], 1);  // col
    }
}

// one block, 1024 threads: exclusive scan of BOTH (deg rounded up to 8) arrays per chunk
__global__ void scan_two() {
    __shared__ int wsumc[33], wsumr[33];
    const int tid = threadIdx.x, lane = tid & 31, wid = tid >> 5;
    int runc = 0, runr = 0;
    for (int base = 0; base < NN; base += 1024) {
        int i = base + tid;
        int vc = (i < NN) ? ((g_degc[i] + 7) & ~7) : 0;
        int vr = (i < NN) ? ((g_degr[i] + 7) & ~7) : 0;
        int incc = vc, incr = vr;
        #pragma unroll
        for (int o = 1; o < 32; o <<= 1) {
            int tc = __shfl_up_sync(0xffffffffu, incc, o);
            int tr = __shfl_up_sync(0xffffffffu, incr, o);
            if (lane >= o) { incc += tc; incr += tr; }
        }
        if (lane == 31) { wsumc[wid] = incc; wsumr[wid] = incr; }
        __syncthreads();
        if (wid == 0) {
            int sc = wsumc[lane], sr = wsumr[lane];
            int sic = sc, sir = sr;
            #pragma unroll
            for (int o = 1; o < 32; o <<= 1) {
                int tc = __shfl_up_sync(0xffffffffu, sic, o);
                int tr = __shfl_up_sync(0xffffffffu, sir, o);
                if (lane >= o) { sic += tc; sir += tr; }
            }
            wsumc[lane] = sic - sc;
            wsumr[lane] = sir - sr;
            if (lane == 31) { wsumc[32] = sic; wsumr[32] = sir; }
        }
        __syncthreads();
        if (i < NN) {
            g_offc[i] = runc + wsumc[wid] + incc - vc;
            g_offr[i] = runr + wsumr[wid] + incr - vr;
        }
        runc += wsumc[32];
        runr += wsumr[32];
        __syncthreads();
    }
    if (tid == 0) { g_offc[NN] = runc; g_offr[NN] = runr; }
}

__global__ void node_init() {
    for (int i = blockIdx.x * blockDim.x + threadIdx.x; i < NN;
         i += gridDim.x * blockDim.x) {
        g_curc[i] = g_offc[i];
        g_curr[i] = g_offr[i];
        g_dinv[i] = rsqrtf((float)(g_degc[i] + 1));  // +1 self loop
        g_cntinv[i] = 1.0f / fmaxf((float)g_degr[i], 1.0f);
    }
}

__global__ void scatter_edges(const int* __restrict__ ei) {
    for (int e = blockIdx.x * blockDim.x + threadIdx.x; e < NEDGE;
         e += gridDim.x * blockDim.x) {
        int r = ei[e];
        int c = ei[NEDGE + e];
        int p = atomicAdd(&g_curc[c], 1);
        g_adjc[p] = r;  // CSR by col (gcn target), stores source row
        int q = atomicAdd(&g_curr[r], 1);
        g_adjr[q] = c;  // CSR by row (mean_agg target), stores source col
    }
}

// ---------------- first layer: x@W0*dinv -> Gq ; LN(relu(x@W_res)) -> x0 ----------------
__global__ void kfirst(const float* __restrict__ x, const float* __restrict__ W0,
                       const float* __restrict__ Wres, const float* __restrict__ rg,
                       const float* __restrict__ rb) {
    __shared__ float Wsm[IN_DIM * HID];  // 32 KB
    const int tid = threadIdx.x;
    const int lane = tid & 31;
    const int i = (blockIdx.x * blockDim.x + tid) >> 5;  // node (grid exact)

    for (int k = tid; k < IN_DIM * HID; k += blockDim.x) Wsm[k] = W0[k];

    float xr[8];
    #pragma unroll
    for (int j = 0; j < 8; j++) xr[j] = x[i * IN_DIM + j * 32 + lane];
    __syncthreads();

    float acc0 = 0.f;
    #pragma unroll
    for (int j = 0; j < 8; j++) {
        #pragma unroll
        for (int t = 0; t < 32; t++) {
            float xv = __shfl_sync(0xffffffffu, xr[j], t);
            acc0 = fmaf(xv, Wsm[(j * 32 + t) * HID + lane], acc0);
        }
    }
    __syncthreads();
    for (int k = tid; k < IN_DIM * HID; k += blockDim.x) Wsm[k] = Wres[k];
    __syncthreads();

    float acc1 = 0.f;
    #pragma unroll
    for (int j = 0; j < 8; j++) {
        #pragma unroll
        for (int t = 0; t < 32; t++) {
            float xv = __shfl_sync(0xffffffffu, xr[j], t);
            acc1 = fmaf(xv, Wsm[(j * 32 + t) * HID + lane], acc1);
        }
    }

    quant_row(i, lane, acc0 * g_dinv[i]);

    float r = fmaxf(acc1, 0.f);
    float m = warpsum(r) * (1.f / HID);
    float d = r - m;
    float var = warpsum(d * d) * (1.f / HID);
    g_x0[i * HID + lane] = d * rsqrtf(var + 1e-5f) * rg[lane] + rb[lane];
}

// ---------------- GCN aggregate + bias + relu + LN -> Bf/Bh (dual-edge int16) ----------------
__global__ void k2_gcn_ln(const float* __restrict__ b, const float* __restrict__ gam,
                          const float* __restrict__ bet) {
    const int lane = threadIdx.x & 31;
    const int sub = lane & 15;     // feature-pair index
    const int half = lane >> 4;    // which edge of the pair
    const int i = (blockIdx.x * blockDim.x + threadIdx.x) >> 5;
    if (i >= NN) return;
    const short2* Q2 = (const short2*)g_Gq;
    const int s = g_offc[i];
    const int e = s + g_degc[i];
    int p = s;
    float2 a0 = {0.f, 0.f}, a1 = {0.f, 0.f}, a2 = {0.f, 0.f}, a3 = {0.f, 0.f};
    for (; p + 8 <= e; p += 8) {
        int4 ia = *(const int4*)&g_adjc[p];
        int4 ib = *(const int4*)&g_adjc[p + 4];
        int j0 = half ? ia.y : ia.x, j1 = half ? ia.w : ia.z;
        int j2 = half ? ib.y : ib.x, j3 = half ? ib.w : ib.z;
        float s0 = g_GS[j0], s1 = g_GS[j1], s2 = g_GS[j2], s3 = g_GS[j3];
        short2 v0 = Q2[j0 * 16 + sub];
        short2 v1 = Q2[j1 * 16 + sub];
        short2 v2 = Q2[j2 * 16 + sub];
        short2 v3 = Q2[j3 * 16 + sub];
        a0.x = fmaf(s0, (float)v0.x, a0.x); a0.y = fmaf(s0, (float)v0.y, a0.y);
        a1.x = fmaf(s1, (float)v1.x, a1.x); a1.y = fmaf(s1, (float)v1.y, a1.y);
        a2.x = fmaf(s2, (float)v2.x, a2.x); a2.y = fmaf(s2, (float)v2.y, a2.y);
        a3.x = fmaf(s3, (float)v3.x, a3.x); a3.y = fmaf(s3, (float)v3.y, a3.y);
    }
    for (; p < e; p += 2) {
        if (p + half < e) {
            int j = g_adjc[p + half];
            float sj = g_GS[j];
            short2 v = Q2[j * 16 + sub];
            a0.x = fmaf(sj, (float)v.x, a0.x);
            a0.y = fmaf(sj, (float)v.y, a0.y);
        }
    }
    float sx = (a0.x + a1.x) + (a2.x + a3.x);
    float sy = (a0.y + a1.y) + (a2.y + a3.y);
    sx += __shfl_xor_sync(0xffffffffu, sx, 16);   // combine halves
    sy += __shfl_xor_sync(0xffffffffu, sy, 16);
    {
        short2 self = Q2[i * 16 + sub];           // self loop
        float si = g_GS[i];
        sx = fmaf(si, (float)self.x, sx);
        sy = fmaf(si, (float)self.y, sy);
    }
    const float dv = g_dinv[i];
    float2 bb = ((const float2*)b)[sub];
    float v0 = fmaxf(fmaf(dv, sx, bb.x), 0.f);
    float v1 = fmaxf(fmaf(dv, sy, bb.y), 0.f);
    // LN over 32 features; lanes duplicate features across halves -> x0.5
    float m = warpsum(v0 + v1) * (0.5f / HID);
    float d0 = v0 - m, d1 = v1 - m;
    float var = warpsum(d0 * d0 + d1 * d1) * (0.5f / HID);
    float rs = rsqrtf(var + 1e-5f);
    float2 gg = ((const float2*)gam)[sub];
    float2 be = ((const float2*)bet)[sub];
    float o0 = d0 * rs * gg.x + be.x;
    float o1 = d1 * rs * gg.y + be.y;
    if (half == 0) {
        ((float2*)g_Bf)[i * 16 + sub] = make_float2(o0, o1);
        ((__half2*)g_Bh)[i * 16 + sub] = __floats2half2_rn(o0, o1);
    }
}

// ---------------- mean_agg(B)->hm ; scalars s,t (dual-edge, 8-wide: R6) ----------------
__global__ void k3_mean(const float* __restrict__ w_ws) {
    const int lane = threadIdx.x & 31;
    const int sub = lane & 15;
    const int half = lane >> 4;
    const int i = (blockIdx.x * blockDim.x + threadIdx.x) >> 5;
    if (i >= NN) return;
    const __half2* B2 = (const __half2*)g_Bh;
    const int s = g_offr[i];
    const int e = s + g_degr[i];
    int p = s;
    float2 a0 = {0.f, 0.f}, a1 = {0.f, 0.f}, a2 = {0.f, 0.f}, a3 = {0.f, 0.f};
    for (; p + 8 <= e; p += 8) {
        int4 ia = *(const int4*)&g_adjr[p];
        int4 ib = *(const int4*)&g_adjr[p + 4];
        int j0 = half ? ia.y : ia.x, j1 = half ? ia.w : ia.z;
        int j2 = half ? ib.y : ib.x, j3 = half ? ib.w : ib.z;
        float2 v0 = __half22float2(B2[j0 * 16 + sub]);
        float2 v1 = __half22float2(B2[j1 * 16 + sub]);
        float2 v2 = __half22float2(B2[j2 * 16 + sub]);
        float2 v3 = __half22float2(B2[j3 * 16 + sub]);
        a0.x += v0.x; a0.y += v0.y;
        a1.x += v1.x; a1.y += v1.y;
        a2.x += v2.x; a2.y += v2.y;
        a3.x += v3.x; a3.y += v3.y;
    }
    for (; p < e; p += 2) {
        if (p + half < e) {
            float2 v = __half22float2(B2[g_adjr[p + half] * 16 + sub]);
            a0.x += v.x; a0.y += v.y;
        }
    }
    float sx = (a0.x + a1.x) + (a2.x + a3.x);
    float sy = (a0.y + a1.y) + (a2.y + a3.y);
    sx += __shfl_xor_sync(0xffffffffu, sx, 16);
    sy += __shfl_xor_sync(0xffffffffu, sy, 16);
    const float ci = g_cntinv[i];
    float hm0 = sx * ci, hm1 = sy * ci;
    float2 h = ((const float2*)g_Bf)[i * 16 + sub];
    float2 w0 = ((const float2*)w_ws)[sub];
    float2 w2 = ((const float2*)(w_ws + HID))[sub];
    float svp = fabsf(h.x - hm0) * w2.x + fabsf(h.y - hm1) * w2.y;
    float tvp = hm0 * h.x * w0.x + hm1 * h.y * w0.y;
    float sv = warpsum(svp) * 0.5f;   // halves duplicate
    float tv = warpsum(tvp) * 0.5f;
    if (lane == 0) {
        g_S[i] = sv;
        g_T[i] = tv;
    }
}

// ---------------- scalar gather s -> hd ; score ; gate ; fused GEMM -> Gq ----------------
__global__ void k4_score_gemm(const float* __restrict__ w_ws, const float* __restrict__ W) {
    __shared__ float Wsm[HID * HID];
    const int tid = threadIdx.x;
    const int lane = tid & 31;
    const int i = (blockIdx.x * blockDim.x + tid) >> 5;
    for (int k = tid; k < HID * HID; k += blockDim.x) Wsm[k] = W[k];
    __syncthreads();
    if (i >= NN) return;
    const int s = g_offr[i];
    const int e = s + g_degr[i];
    float sum = 0.f;  // lane-parallel over edges
    for (int p = s + lane; p < e; p += 32) sum += __ldg(&g_S[g_adjr[p]]);
    float hd = warpsum(sum) * g_cntinv[i];
    float h = g_Bf[i * HID + lane];
    float sc = warpsum(h * w_ws[64 + lane]) + g_T[i] + hd;
    sc = 1.0f / (1.0f + expf(-sc));
    float hnew = (1.0f - sc) * h + sc * g_x0[i * HID + lane];
    // fused next-layer GEMM: Gq = quant((hnew @ W) * dinv)
    float g = 0.f;
    #pragma unroll
    for (int t = 0; t < HID; t++)
        g = fmaf(__shfl_sync(0xffffffffu, hnew, t), Wsm[t * HID + lane], g);
    quant_row(i, lane, g * g_dinv[i]);
}

// ---------------- last block: score + gate + fused CLASSIFIER GEMM -> G40h (fp16) -------
__global__ void k4_last_gemm(const float* __restrict__ w_ws, const float* __restrict__ Wl) {
    __shared__ float Wsm[HID * NCLS];  // 5 KB
    const int tid = threadIdx.x;
    const int lane = tid & 31;
    const int i = (blockIdx.x * blockDim.x + tid) >> 5;
    for (int k = tid; k < HID * NCLS; k += blockDim.x) Wsm[k] = Wl[k];
    __syncthreads();
    if (i >= NN) return;
    const int s = g_offr[i];
    const int e = s + g_degr[i];
    float sum = 0.f;
    for (int p = s + lane; p < e; p += 32) sum += __ldg(&g_S[g_adjr[p]]);
    float hd = warpsum(sum) * g_cntinv[i];
    float h = g_Bf[i * HID + lane];
    float sc = warpsum(h * w_ws[64 + lane]) + g_T[i] + hd;
    sc = 1.0f / (1.0f + expf(-sc));
    float hnew = (1.0f - sc) * h + sc * g_x0[i * HID + lane];
    // classifier GEMM: G40 = (hnew @ Wl) * dinv, stored fp16 (final layer only)
    float acc0 = 0.f, acc1 = 0.f;
    #pragma unroll
    for (int t = 0; t < HID; t++) {
        float xv = __shfl_sync(0xffffffffu, hnew, t);
        acc0 = fmaf(xv, Wsm[t * NCLS + lane], acc0);
        if (lane < 8) acc1 = fmaf(xv, Wsm[t * NCLS + 32 + lane], acc1);
    }
    float dv = g_dinv[i];
    g_G40h[i * NCLS + lane] = __float2half_rn(acc0 * dv);
    if (lane < 8) g_G40h[i * NCLS + 32 + lane] = __float2half_rn(acc1 * dv);
}

// ---------------- final GCN aggregate (fp16 gather) -> out ----------------
__global__ void k2_final(const float* __restrict__ bl, float* __restrict__ out) {
    const int lane = threadIdx.x & 31;
    const int i = (blockIdx.x * blockDim.x + threadIdx.x) >> 5;
    if (i >= NN) return;
    float acc0 = __half2float(g_G40h[i * NCLS + lane]);
    float acc1 = (lane < 8) ? __half2float(g_G40h[i * NCLS + 32 + lane]) : 0.f;
    const int s = g_offc[i];
    const int e = s + g_degc[i];
    int p = s;
    float b0 = 0.f, b1 = 0.f, b2 = 0.f, b3 = 0.f;
    float c0 = 0.f, c1 = 0.f, c2 = 0.f, c3 = 0.f;
    for (; p + 3 < e; p += 4) {
        int i0 = g_adjc[p], i1 = g_adjc[p + 1], i2 = g_adjc[p + 2], i3 = g_adjc[p + 3];
        b0 += __half2float(g_G40h[i0 * NCLS + lane]);
        b1 += __half2float(g_G40h[i1 * NCLS + lane]);
        b2 += __half2float(g_G40h[i2 * NCLS + lane]);
        b3 += __half2float(g_G40h[i3 * NCLS + lane]);
        if (lane < 8) {
            c0 += __half2float(g_G40h[i0 * NCLS + 32 + lane]);
            c1 += __half2float(g_G40h[i1 * NCLS + 32 + lane]);
            c2 += __half2float(g_G40h[i2 * NCLS + 32 + lane]);
            c3 += __half2float(g_G40h[i3 * NCLS + 32 + lane]);
        }
    }
    for (; p < e; p++) {
        int idx = g_adjc[p];
        acc0 += __half2float(g_G40h[idx * NCLS + lane]);
        if (lane < 8) acc1 += __half2float(g_G40h[idx * NCLS + 32 + lane]);
    }
    acc0 += (b0 + b1) + (b2 + b3);
    acc1 += (c0 + c1) + (c2 + c3);
    float dv = g_dinv[i];
    out[i * NCLS + lane] = dv * acc0 + bl[lane];
    if (lane < 8) out[i * NCLS + 32 + lane] = dv * acc1 + bl[32 + lane];
}

// ---------------- host ----------------
extern "C" void kernel_launch(void* const* d_in, const int* in_sizes, int n_in,
                              void* d_out, int out_size) {
    const float* x    = (const float*)d_in[0];
    const int*   ei   = (const int*)d_in[1];
    const float* W0   = (const float*)d_in[2];
    const float* b0   = (const float*)d_in[3];
    const float* Whh  = (const float*)d_in[4];
    const float* bhh  = (const float*)d_in[5];
    const float* Wl   = (const float*)d_in[6];
    const float* bl   = (const float*)d_in[7];
    const float* lng0 = (const float*)d_in[8];
    const float* lnb0 = (const float*)d_in[9];
    const float* lngm = (const float*)d_in[10];
    const float* lnbm = (const float*)d_in[11];
    const float* w_ws = (const float*)d_in[12];
    const float* Wres = (const float*)d_in[13];
    const float* rg   = (const float*)d_in[14];
    const float* rb   = (const float*)d_in[15];
    float* out = (float*)d_out;

    const int nodeBlocks = (NN + 255) / 256;
    const int warpBlocks = (NN * 32 + 255) / 256;  // warp-per-node, 8 nodes/block

    // CSR build
    zero_deg<<<nodeBlocks, 256>>>();
    hist_edges<<<2048, 256>>>(ei);
    scan_two<<<1, 1024>>>();
    node_init<<<nodeBlocks, 256>>>();
    scatter_edges<<<2048, 256>>>(ei);

    // first layer
    kfirst<<<warpBlocks, 256>>>(x, W0, Wres, rg, rb);

    for (int l = 0; l <= NMID; l++) {  // blocks 0..30
        const float* b   = (l == 0) ? b0   : bhh  + (l - 1) * HID;
        const float* gam = (l == 0) ? lng0 : lngm + (l - 1) * HID;
        const float* bet = (l == 0) ? lnb0 : lnbm + (l - 1) * HID;
        k2_gcn_ln<<<warpBlocks, 256>>>(b, gam, bet);
        k3_mean<<<warpBlocks, 256>>>(w_ws);
        if (l < NMID) {
            k4_score_gemm<<<warpBlocks, 256>>>(w_ws, Whh + l * HID * HID);
        } else {
            k4_last_gemm<<<warpBlocks, 256>>>(w_ws, Wl);
        }
    }
    k2_final<<<warpBlocks, 256>>>(bl, out);
}

// round 17
// speedup vs baseline: 1.0943x; 1.0943x over previous
#include <cuda_runtime.h>
#include <cuda_fp16.h>
#include <math.h>

#define NN 50000
#define IN_DIM 256
#define HID 32
#define NCLS 40
#define NEDGE 1600000
#define NMID 30
#define ADJCAP (NEDGE + 8 * NN)   // rows padded to multiples of 8

// ---------------- device scratch (no allocations allowed) ----------------
__device__ int    g_degc[NN], g_degr[NN];
__device__ int    g_offc[NN + 1], g_offr[NN + 1];   // 8-aligned row starts
__device__ int    g_curc[NN], g_curr[NN];
__device__ __align__(16) unsigned short g_adjc16[ADJCAP];
__device__ __align__(16) unsigned short g_adjr16[ADJCAP];
__device__ float  g_dinv[NN], g_cntinv[NN];
__device__ float  g_x0[NN * HID];
__device__ __align__(16) float  g_G [NN * HID];   // (h @ W) * dinv — gathered fp32
__device__ __align__(16) float  g_Bf[NN * HID];   // LN(relu(gcn)) — node-local fp32
__device__ __align__(16) __half g_Bh[NN * HID];   // fp16 gather copy (score path)
__device__ float  g_S[NN];           // s[j]=Σ|B-hm|·w2  — scalar gathered fp32
__device__ float  g_T[NN];           // t[i]=Σ hm·h·w0   — node-local scalar
__device__ __half g_G40h[NN * NCLS]; // final (h @ Wl) * dinv — fp16 (one layer only)

__device__ __forceinline__ float warpsum(float v) {
    #pragma unroll
    for (int o = 16; o > 0; o >>= 1) v += __shfl_xor_sync(0xffffffffu, v, o);
    return v;
}

// ---------------- setup: degrees, scans, CSR ----------------
__global__ void zero_deg() {
    for (int i = blockIdx.x * blockDim.x + threadIdx.x; i < NN;
         i += gridDim.x * blockDim.x) {
        g_degc[i] = 0;
        g_degr[i] = 0;
    }
}

__global__ void hist_edges(const int* __restrict__ ei) {
    for (int e = blockIdx.x * blockDim.x + threadIdx.x; e < NEDGE;
         e += gridDim.x * blockDim.x) {
        atomicAdd(&g_degr[ei[e]], 1);          // row
        atomicAdd(&g_degc[ei[NEDGE + e]], 1);  // col
    }
}

// one block, 1024 threads: exclusive scan of BOTH (deg rounded up to 8) arrays per chunk
__global__ void scan_two() {
    __shared__ int wsumc[33], wsumr[33];
    const int tid = threadIdx.x, lane = tid & 31, wid = tid >> 5;
    int runc = 0, runr = 0;
    for (int base = 0; base < NN; base += 1024) {
        int i = base + tid;
        int vc = (i < NN) ? ((g_degc[i] + 7) & ~7) : 0;
        int vr = (i < NN) ? ((g_degr[i] + 7) & ~7) : 0;
        int incc = vc, incr = vr;
        #pragma unroll
        for (int o = 1; o < 32; o <<= 1) {
            int tc = __shfl_up_sync(0xffffffffu, incc, o);
            int tr = __shfl_up_sync(0xffffffffu, incr, o);
            if (lane >= o) { incc += tc; incr += tr; }
        }
        if (lane == 31) { wsumc[wid] = incc; wsumr[wid] = incr; }
        __syncthreads();
        if (wid == 0) {
            int sc = wsumc[lane], sr = wsumr[lane];
            int sic = sc, sir = sr;
            #pragma unroll
            for (int o = 1; o < 32; o <<= 1) {
                int tc = __shfl_up_sync(0xffffffffu, sic, o);
                int tr = __shfl_up_sync(0xffffffffu, sir, o);
                if (lane >= o) { sic += tc; sir += tr; }
            }
            wsumc[lane] = sic - sc;
            wsumr[lane] = sir - sr;
            if (lane == 31) { wsumc[32] = sic; wsumr[32] = sir; }
        }
        __syncthreads();
        if (i < NN) {
            g_offc[i] = runc + wsumc[wid] + incc - vc;
            g_offr[i] = runr + wsumr[wid] + incr - vr;
        }
        runc += wsumc[32];
        runr += wsumr[32];
        __syncthreads();
    }
    if (tid == 0) { g_offc[NN] = runc; g_offr[NN] = runr; }
}

__global__ void node_init() {
    for (int i = blockIdx.x * blockDim.x + threadIdx.x; i < NN;
         i += gridDim.x * blockDim.x) {
        g_curc[i] = g_offc[i];
        g_curr[i] = g_offr[i];
        g_dinv[i] = rsqrtf((float)(g_degc[i] + 1));  // +1 self loop
        g_cntinv[i] = 1.0f / fmaxf((float)g_degr[i], 1.0f);
    }
}

__global__ void scatter_edges(const int* __restrict__ ei) {
    for (int e = blockIdx.x * blockDim.x + threadIdx.x; e < NEDGE;
         e += gridDim.x * blockDim.x) {
        int r = ei[e];
        int c = ei[NEDGE + e];
        int p = atomicAdd(&g_curc[c], 1);
        g_adjc16[p] = (unsigned short)r;  // CSR by col (gcn target), stores source row
        int q = atomicAdd(&g_curr[r], 1);
        g_adjr16[q] = (unsigned short)c;  // CSR by row (mean_agg target), stores source col
    }
}

// ---------------- first layer: x@W0*dinv -> G ; LN(relu(x@W_res)) -> x0 ----------------
__global__ void kfirst(const float* __restrict__ x, const float* __restrict__ W0,
                       const float* __restrict__ Wres, const float* __restrict__ rg,
                       const float* __restrict__ rb) {
    __shared__ float Wsm[IN_DIM * HID];  // 32 KB
    const int tid = threadIdx.x;
    const int lane = tid & 31;
    const int i = (blockIdx.x * blockDim.x + tid) >> 5;  // node (grid exact)

    for (int k = tid; k < IN_DIM * HID; k += blockDim.x) Wsm[k] = W0[k];

    float xr[8];
    #pragma unroll
    for (int j = 0; j < 8; j++) xr[j] = x[i * IN_DIM + j * 32 + lane];
    __syncthreads();

    float acc0 = 0.f;
    #pragma unroll
    for (int j = 0; j < 8; j++) {
        #pragma unroll
        for (int t = 0; t < 32; t++) {
            float xv = __shfl_sync(0xffffffffu, xr[j], t);
            acc0 = fmaf(xv, Wsm[(j * 32 + t) * HID + lane], acc0);
        }
    }
    __syncthreads();
    for (int k = tid; k < IN_DIM * HID; k += blockDim.x) Wsm[k] = Wres[k];
    __syncthreads();

    float acc1 = 0.f;
    #pragma unroll
    for (int j = 0; j < 8; j++) {
        #pragma unroll
        for (int t = 0; t < 32; t++) {
            float xv = __shfl_sync(0xffffffffu, xr[j], t);
            acc1 = fmaf(xv, Wsm[(j * 32 + t) * HID + lane], acc1);
        }
    }

    g_G[i * HID + lane] = acc0 * g_dinv[i];

    float r = fmaxf(acc1, 0.f);
    float m = warpsum(r) * (1.f / HID);
    float d = r - m;
    float var = warpsum(d * d) * (1.f / HID);
    g_x0[i * HID + lane] = d * rsqrtf(var + 1e-5f) * rg[lane] + rb[lane];
}

// ---------------- GCN aggregate + bias + relu + LN -> Bf/Bh (dual-edge, uint16 idx) -----
__global__ void k2_gcn_ln(const float* __restrict__ b, const float* __restrict__ gam,
                          const float* __restrict__ bet) {
    const int lane = threadIdx.x & 31;
    const int sub = lane & 15;     // feature-pair index
    const int half = lane >> 4;    // which edge of the pair
    const int i = (blockIdx.x * blockDim.x + threadIdx.x) >> 5;
    if (i >= NN) return;
    const float2* G2 = (const float2*)g_G;
    const int s = g_offc[i];
    const int e = s + g_degc[i];
    int p = s;
    float2 a0 = {0.f, 0.f}, a1 = {0.f, 0.f}, a2 = {0.f, 0.f}, a3 = {0.f, 0.f};
    for (; p + 8 <= e; p += 8) {
        uint4 iw = *(const uint4*)&g_adjc16[p];   // 8 uint16 indices in ONE load
        int j0 = half ? (int)(iw.x >> 16) : (int)(iw.x & 0xffffu);
        int j1 = half ? (int)(iw.y >> 16) : (int)(iw.y & 0xffffu);
        int j2 = half ? (int)(iw.z >> 16) : (int)(iw.z & 0xffffu);
        int j3 = half ? (int)(iw.w >> 16) : (int)(iw.w & 0xffffu);
        float2 v0 = G2[j0 * 16 + sub];
        float2 v1 = G2[j1 * 16 + sub];
        float2 v2 = G2[j2 * 16 + sub];
        float2 v3 = G2[j3 * 16 + sub];
        a0.x += v0.x; a0.y += v0.y;
        a1.x += v1.x; a1.y += v1.y;
        a2.x += v2.x; a2.y += v2.y;
        a3.x += v3.x; a3.y += v3.y;
    }
    for (; p < e; p += 2) {
        if (p + half < e) {
            int j = (int)g_adjc16[p + half];
            float2 v = G2[j * 16 + sub];
            a0.x += v.x; a0.y += v.y;
        }
    }
    float sx = (a0.x + a1.x) + (a2.x + a3.x);
    float sy = (a0.y + a1.y) + (a2.y + a3.y);
    sx += __shfl_xor_sync(0xffffffffu, sx, 16);   // combine halves
    sy += __shfl_xor_sync(0xffffffffu, sy, 16);
    float2 self = G2[i * 16 + sub];               // self loop
    sx += self.x;
    sy += self.y;
    const float dv = g_dinv[i];
    float2 bb = ((const float2*)b)[sub];
    float v0 = fmaxf(fmaf(dv, sx, bb.x), 0.f);
    float v1 = fmaxf(fmaf(dv, sy, bb.y), 0.f);
    // LN over 32 features; lanes duplicate features across halves -> x0.5
    float m = warpsum(v0 + v1) * (0.5f / HID);
    float d0 = v0 - m, d1 = v1 - m;
    float var = warpsum(d0 * d0 + d1 * d1) * (0.5f / HID);
    float rs = rsqrtf(var + 1e-5f);
    float2 gg = ((const float2*)gam)[sub];
    float2 be = ((const float2*)bet)[sub];
    float o0 = d0 * rs * gg.x + be.x;
    float o1 = d1 * rs * gg.y + be.y;
    if (half == 0) {
        ((float2*)g_Bf)[i * 16 + sub] = make_float2(o0, o1);
        ((__half2*)g_Bh)[i * 16 + sub] = __floats2half2_rn(o0, o1);
    }
}

// ---------------- mean_agg(B)->hm ; scalars s,t (dual-edge, uint16 idx) ----------------
__global__ void k3_mean(const float* __restrict__ w_ws) {
    const int lane = threadIdx.x & 31;
    const int sub = lane & 15;
    const int half = lane >> 4;
    const int i = (blockIdx.x * blockDim.x + threadIdx.x) >> 5;
    if (i >= NN) return;
    const __half2* B2 = (const __half2*)g_Bh;
    const int s = g_offr[i];
    const int e = s + g_degr[i];
    int p = s;
    float2 a0 = {0.f, 0.f}, a1 = {0.f, 0.f}, a2 = {0.f, 0.f}, a3 = {0.f, 0.f};
    for (; p + 8 <= e; p += 8) {
        uint4 iw = *(const uint4*)&g_adjr16[p];
        int j0 = half ? (int)(iw.x >> 16) : (int)(iw.x & 0xffffu);
        int j1 = half ? (int)(iw.y >> 16) : (int)(iw.y & 0xffffu);
        int j2 = half ? (int)(iw.z >> 16) : (int)(iw.z & 0xffffu);
        int j3 = half ? (int)(iw.w >> 16) : (int)(iw.w & 0xffffu);
        float2 v0 = __half22float2(B2[j0 * 16 + sub]);
        float2 v1 = __half22float2(B2[j1 * 16 + sub]);
        float2 v2 = __half22float2(B2[j2 * 16 + sub]);
        float2 v3 = __half22float2(B2[j3 * 16 + sub]);
        a0.x += v0.x; a0.y += v0.y;
        a1.x += v1.x; a1.y += v1.y;
        a2.x += v2.x; a2.y += v2.y;
        a3.x += v3.x; a3.y += v3.y;
    }
    for (; p < e; p += 2) {
        if (p + half < e) {
            float2 v = __half22float2(B2[(int)g_adjr16[p + half] * 16 + sub]);
            a0.x += v.x; a0.y += v.y;
        }
    }
    float sx = (a0.x + a1.x) + (a2.x + a3.x);
    float sy = (a0.y + a1.y) + (a2.y + a3.y);
    sx += __shfl_xor_sync(0xffffffffu, sx, 16);
    sy += __shfl_xor_sync(0xffffffffu, sy, 16);
    const float ci = g_cntinv[i];
    float hm0 = sx * ci, hm1 = sy * ci;
    float2 h = ((const float2*)g_Bf)[i * 16 + sub];
    float2 w0 = ((const float2*)w_ws)[sub];
    float2 w2 = ((const float2*)(w_ws + HID))[sub];
    float svp = fabsf(h.x - hm0) * w2.x + fabsf(h.y - hm1) * w2.y;
    float tvp = hm0 * h.x * w0.x + hm1 * h.y * w0.y;
    float sv = warpsum(svp) * 0.5f;   // halves duplicate
    float tv = warpsum(tvp) * 0.5f;
    if (lane == 0) {
        g_S[i] = sv;
        g_T[i] = tv;
    }
}

// ---------------- scalar gather s -> hd ; score ; gate ; fused GEMM -> G ----------------
__global__ void k4_score_gemm(const float* __restrict__ w_ws, const float* __restrict__ W) {
    __shared__ float Wsm[HID * HID];
    const int tid = threadIdx.x;
    const int lane = tid & 31;
    const int i = (blockIdx.x * blockDim.x + tid) >> 5;
    for (int k = tid; k < HID * HID; k += blockDim.x) Wsm[k] = W[k];
    __syncthreads();
    if (i >= NN) return;
    const int s = g_offr[i];
    const int e = s + g_degr[i];
    float sum = 0.f;  // lane-parallel over edges
    for (int p = s + lane; p < e; p += 32) sum += __ldg(&g_S[(int)g_adjr16[p]]);
    float hd = warpsum(sum) * g_cntinv[i];
    float h = g_Bf[i * HID + lane];
    float sc = warpsum(h * w_ws[64 + lane]) + g_T[i] + hd;
    sc = 1.0f / (1.0f + expf(-sc));
    float hnew = (1.0f - sc) * h + sc * g_x0[i * HID + lane];
    // fused next-layer GEMM: G = (hnew @ W) * dinv
    float g = 0.f;
    #pragma unroll
    for (int t = 0; t < HID; t++)
        g = fmaf(__shfl_sync(0xffffffffu, hnew, t), Wsm[t * HID + lane], g);
    g_G[i * HID + lane] = g * g_dinv[i];
}

// ---------------- last block: score + gate + fused CLASSIFIER GEMM -> G40h (fp16) -------
__global__ void k4_last_gemm(const float* __restrict__ w_ws, const float* __restrict__ Wl) {
    __shared__ float Wsm[HID * NCLS];  // 5 KB
    const int tid = threadIdx.x;
    const int lane = tid & 31;
    const int i = (blockIdx.x * blockDim.x + tid) >> 5;
    for (int k = tid; k < HID * NCLS; k += blockDim.x) Wsm[k] = Wl[k];
    __syncthreads();
    if (i >= NN) return;
    const int s = g_offr[i];
    const int e = s + g_degr[i];
    float sum = 0.f;
    for (int p = s + lane; p < e; p += 32) sum += __ldg(&g_S[(int)g_adjr16[p]]);
    float hd = warpsum(sum) * g_cntinv[i];
    float h = g_Bf[i * HID + lane];
    float sc = warpsum(h * w_ws[64 + lane]) + g_T[i] + hd;
    sc = 1.0f / (1.0f + expf(-sc));
    float hnew = (1.0f - sc) * h + sc * g_x0[i * HID + lane];
    // classifier GEMM: G40 = (hnew @ Wl) * dinv, stored fp16 (final layer only)
    float acc0 = 0.f, acc1 = 0.f;
    #pragma unroll
    for (int t = 0; t < HID; t++) {
        float xv = __shfl_sync(0xffffffffu, hnew, t);
        acc0 = fmaf(xv, Wsm[t * NCLS + lane], acc0);
        if (lane < 8) acc1 = fmaf(xv, Wsm[t * NCLS + 32 + lane], acc1);
    }
    float dv = g_dinv[i];
    g_G40h[i * NCLS + lane] = __float2half_rn(acc0 * dv);
    if (lane < 8) g_G40h[i * NCLS + 32 + lane] = __float2half_rn(acc1 * dv);
}

// ---------------- final GCN aggregate (fp16 gather) -> out ----------------
__global__ void k2_final(const float* __restrict__ bl, float* __restrict__ out) {
    const int lane = threadIdx.x & 31;
    const int i = (blockIdx.x * blockDim.x + threadIdx.x) >> 5;
    if (i >= NN) return;
    float acc0 = __half2float(g_G40h[i * NCLS + lane]);
    float acc1 = (lane < 8) ? __half2float(g_G40h[i * NCLS + 32 + lane]) : 0.f;
    const int s = g_offc[i];
    const int e = s + g_degc[i];
    int p = s;
    float b0 = 0.f, b1 = 0.f, b2 = 0.f, b3 = 0.f;
    float c0 = 0.f, c1 = 0.f, c2 = 0.f, c3 = 0.f;
    for (; p + 3 < e; p += 4) {
        int i0 = (int)g_adjc16[p],     i1 = (int)g_adjc16[p + 1];
        int i2 = (int)g_adjc16[p + 2], i3 = (int)g_adjc16[p + 3];
        b0 += __half2float(g_G40h[i0 * NCLS + lane]);
        b1 += __half2float(g_G40h[i1 * NCLS + lane]);
        b2 += __half2float(g_G40h[i2 * NCLS + lane]);
        b3 += __half2float(g_G40h[i3 * NCLS + lane]);
        if (lane < 8) {
            c0 += __half2float(g_G40h[i0 * NCLS + 32 + lane]);
            c1 += __half2float(g_G40h[i1 * NCLS + 32 + lane]);
            c2 += __half2float(g_G40h[i2 * NCLS + 32 + lane]);
            c3 += __half2float(g_G40h[i3 * NCLS + 32 + lane]);
        }
    }
    for (; p < e; p++) {
        int idx = (int)g_adjc16[p];
        acc0 += __half2float(g_G40h[idx * NCLS + lane]);
        if (lane < 8) acc1 += __half2float(g_G40h[idx * NCLS + 32 + lane]);
    }
    acc0 += (b0 + b1) + (b2 + b3);
    acc1 += (c0 + c1) + (c2 + c3);
    float dv = g_dinv[i];
    out[i * NCLS + lane] = dv * acc0 + bl[lane];
    if (lane < 8) out[i * NCLS + 32 + lane] = dv * acc1 + bl[32 + lane];
}

// ---------------- host ----------------
extern "C" void kernel_launch(void* const* d_in, const int* in_sizes, int n_in,
                              void* d_out, int out_size) {
    const float* x    = (const float*)d_in[0];
    const int*   ei   = (const int*)d_in[1];
    const float* W0   = (const float*)d_in[2];
    const float* b0   = (const float*)d_in[3];
    const float* Whh  = (const float*)d_in[4];
    const float* bhh  = (const float*)d_in[5];
    const float* Wl   = (const float*)d_in[6];
    const float* bl   = (const float*)d_in[7];
    const float* lng0 = (const float*)d_in[8];
    const float* lnb0 = (const float*)d_in[9];
    const float* lngm = (const float*)d_in[10];
    const float* lnbm = (const float*)d_in[11];
    const float* w_ws = (const float*)d_in[12];
    const float* Wres = (const float*)d_in[13];
    const float* rg   = (const float*)d_in[14];
    const float* rb   = (const float*)d_in[15];
    float* out = (float*)d_out;

    const int nodeBlocks = (NN + 255) / 256;
    const int warpBlocks = (NN * 32 + 255) / 256;  // warp-per-node, 8 nodes/block

    // CSR build
    zero_deg<<<nodeBlocks, 256>>>();
    hist_edges<<<2048, 256>>>(ei);
    scan_two<<<1, 1024>>>();
    node_init<<<nodeBlocks, 256>>>();
    scatter_edges<<<2048, 256>>>(ei);

    // first layer
    kfirst<<<warpBlocks, 256>>>(x, W0, Wres, rg, rb);

    for (int l = 0; l <= NMID; l++) {  // blocks 0..30
        const float* b   = (l == 0) ? b0   : bhh  + (l - 1) * HID;
        const float* gam = (l == 0) ? lng0 : lngm + (l - 1) * HID;
        const float* bet = (l == 0) ? lnb0 : lnbm + (l - 1) * HID;
        k2_gcn_ln<<<warpBlocks, 256>>>(b, gam, bet);
        k3_mean<<<warpBlocks, 256>>>(w_ws);
        if (l < NMID) {
            k4_score_gemm<<<warpBlocks, 256>>>(w_ws, Whh + l * HID * HID);
        } else {
            k4_last_gemm<<<warpBlocks, 256>>>(w_ws, Wl);
        }
    }
    k2_final<<<warpBlocks, 256>>>(bl, out);
}